// round 1
// baseline (speedup 1.0000x reference)
#include <cuda_runtime.h>
#include <math.h>

// ---------------- problem constants ----------------
#define NMAX 50000
#define EMAX 800000
#define E2MAX (EMAX + NMAX)
#define D 128
#define HMAX 384

// ---------------- scratch (device globals; no mallocs allowed) ----------------
__device__ float g_h [NMAX * D];
__device__ float g_hn[NMAX * D];
__device__ float g_xl[NMAX * D];
__device__ float g_xr[NMAX * D];
__device__ float g_gat[NMAX * D];
__device__ float g_hid[NMAX * HMAX];
__device__ float g_score[E2MAX];
__device__ float g_ex[E2MAX];
__device__ unsigned g_smax[NMAX];
__device__ float g_denom[NMAX];
__device__ float g_pool_s[NMAX];
__device__ float g_hp[D];
__device__ float g_sumw;
__device__ unsigned g_maxu;

// ---------------- helpers ----------------
__device__ __forceinline__ unsigned fenc(float f) {
    unsigned b = __float_as_uint(f);
    return (b & 0x80000000u) ? ~b : (b | 0x80000000u);
}
__device__ __forceinline__ float fdec(unsigned u) {
    return __uint_as_float((u & 0x80000000u) ? (u & 0x7FFFFFFFu) : ~u);
}

#define ACT_NONE 0
#define ACT_RELU 1
#define ACT_GELU 2
#define ACT_TANH 3
#define ACT_SIGM 4

__device__ __forceinline__ float apply_act(float v, int act) {
    switch (act) {
        case ACT_RELU: return v > 0.f ? v : 0.f;
        case ACT_GELU: return 0.5f * v * (1.f + erff(v * 0.70710678118654752f));
        case ACT_TANH: return tanhf(v);
        case ACT_SIGM: return 1.f / (1.f + expf(-v));
        default: return v;
    }
}

// ---------------- zero kernels ----------------
__global__ void zero_f(float* p, int n) {
    int i = blockIdx.x * blockDim.x + threadIdx.x;
    if (i < n) p[i] = 0.f;
}
__global__ void zero_u(unsigned* p, int n) {
    int i = blockIdx.x * blockDim.x + threadIdx.x;
    if (i < n) p[i] = 0u;
}
__global__ void init_pool_kernel() {
    int t = threadIdx.x;
    g_hp[t] = 0.f;
    if (t == 0) { g_sumw = 0.f; g_maxu = 0u; }
}

// ---------------- SGEMM: C[n,M] = act(A[n,K] @ B[K,M] + bias), optional residual add ----------------
// BM=128, BN=128, BK=16, 256 threads, 8x8 per-thread tile.
__global__ void sgemm_kernel(const float* __restrict__ A, const float* __restrict__ B,
                             const float* __restrict__ bias, float* __restrict__ C,
                             int n, int K, int M, int act, int residual)
{
    __shared__ float sA[16][128 + 4];
    __shared__ float sB[16][128 + 4];

    int tid = threadIdx.x;
    int tx = tid & 15;   // col group
    int ty = tid >> 4;   // row group
    int rowBase = blockIdx.x * 128;
    int colBase = blockIdx.y * 128;

    float acc[8][8];
#pragma unroll
    for (int i = 0; i < 8; i++)
#pragma unroll
        for (int j = 0; j < 8; j++) acc[i][j] = 0.f;

    for (int k0 = 0; k0 < K; k0 += 16) {
        // A tile: 128 rows x 16 k
#pragma unroll
        for (int i = 0; i < 8; i++) {
            int idx = tid + 256 * i;
            int r = idx >> 4;
            int kc = idx & 15;
            int gr = rowBase + r;
            float v = 0.f;
            if (gr < n) v = A[(size_t)gr * K + k0 + kc];
            sA[kc][r] = v;
        }
        // B tile: 16 k x 128 cols
#pragma unroll
        for (int i = 0; i < 8; i++) {
            int idx = tid + 256 * i;
            int kr = idx >> 7;
            int c = idx & 127;
            sB[kr + 2 * (i & 0)][c] = 0.f; // dummy to keep shape (removed by compiler)
            sB[(idx >> 7)][c] = B[(size_t)(k0 + (idx >> 7)) * M + colBase + c];
        }
        __syncthreads();
#pragma unroll
        for (int kk = 0; kk < 16; kk++) {
            float ra[8], rb[8];
#pragma unroll
            for (int i = 0; i < 8; i++) ra[i] = sA[kk][ty + 16 * i];
#pragma unroll
            for (int j = 0; j < 8; j++) rb[j] = sB[kk][tx + 16 * j];
#pragma unroll
            for (int i = 0; i < 8; i++)
#pragma unroll
                for (int j = 0; j < 8; j++) acc[i][j] += ra[i] * rb[j];
        }
        __syncthreads();
    }

#pragma unroll
    for (int i = 0; i < 8; i++) {
        int gr = rowBase + ty + 16 * i;
        if (gr >= n) continue;
#pragma unroll
        for (int j = 0; j < 8; j++) {
            int gc = colBase + tx + 16 * j;
            float v = acc[i][j];
            if (bias) v += bias[gc];
            v = apply_act(v, act);
            size_t o = (size_t)gr * M + gc;
            if (residual) C[o] = C[o] + v; else C[o] = v;
        }
    }
}

// ---------------- LayerNorm (warp per row, D=128) ----------------
__global__ void ln_kernel(const float* __restrict__ X, const float* __restrict__ g,
                          const float* __restrict__ b, float* __restrict__ Y, int n)
{
    int w = (blockIdx.x * blockDim.x + threadIdx.x) >> 5;
    int lane = threadIdx.x & 31;
    if (w >= n) return;
    const float* xr = X + (size_t)w * D;
    float v[4], s = 0.f, s2 = 0.f;
#pragma unroll
    for (int i = 0; i < 4; i++) {
        v[i] = xr[lane + 32 * i];
        s += v[i];
        s2 += v[i] * v[i];
    }
#pragma unroll
    for (int off = 16; off > 0; off >>= 1) {
        s  += __shfl_xor_sync(0xFFFFFFFFu, s,  off);
        s2 += __shfl_xor_sync(0xFFFFFFFFu, s2, off);
    }
    float mu = s * (1.f / 128.f);
    float var = s2 * (1.f / 128.f) - mu * mu;
    float rstd = rsqrtf(var + 1e-5f);
    float* yr = Y + (size_t)w * D;
#pragma unroll
    for (int i = 0; i < 4; i++) {
        int d = lane + 32 * i;
        yr[d] = (v[i] - mu) * rstd * g[d] + b[d];
    }
}

// ---------------- GATv2 edge passes ----------------
// pass1: score = lrelu(xl[src]+xr[dst]) . att ; segment max into smax (encoded)
__global__ void edge_score_kernel(const float* __restrict__ xl, const float* __restrict__ xr,
                                  const float* __restrict__ att, const int* __restrict__ ei,
                                  int E, int n)
{
    int e = (blockIdx.x * blockDim.x + threadIdx.x) >> 5;
    int lane = threadIdx.x & 31;
    int E2 = E + n;
    if (e >= E2) return;
    int s_, d_;
    if (e < E) { s_ = ei[e]; d_ = ei[E + e]; } else { s_ = d_ = e - E; }
    float acc = 0.f;
#pragma unroll
    for (int i = 0; i < 4; i++) {
        int d = lane + 32 * i;
        float v = xl[(size_t)s_ * D + d] + xr[(size_t)d_ * D + d];
        v = v > 0.f ? v : 0.2f * v;
        acc += v * att[d];
    }
#pragma unroll
    for (int off = 16; off > 0; off >>= 1) acc += __shfl_xor_sync(0xFFFFFFFFu, acc, off);
    if (lane == 0) {
        g_score[e] = acc;
        atomicMax(&g_smax[d_], fenc(acc));
    }
}

// pass2: ex = exp(score - smax[dst]); denom[dst] += ex
__global__ void edge_exp_kernel(const int* __restrict__ ei, int E, int n)
{
    int e = blockIdx.x * blockDim.x + threadIdx.x;
    int E2 = E + n;
    if (e >= E2) return;
    int d_ = (e < E) ? ei[E + e] : (e - E);
    float ex = expf(g_score[e] - fdec(g_smax[d_]));
    g_ex[e] = ex;
    atomicAdd(&g_denom[d_], ex);
}

// pass3: gat[dst] += (ex/denom[dst]) * xl[src]
__global__ void edge_scatter_kernel(const float* __restrict__ xl, const int* __restrict__ ei,
                                    int E, int n)
{
    int e = (blockIdx.x * blockDim.x + threadIdx.x) >> 5;
    int lane = threadIdx.x & 31;
    int E2 = E + n;
    if (e >= E2) return;
    int s_, d_;
    if (e < E) { s_ = ei[e]; d_ = ei[E + e]; } else { s_ = d_ = e - E; }
    float w = g_ex[e] / g_denom[d_];
#pragma unroll
    for (int i = 0; i < 4; i++) {
        int d = lane + 32 * i;
        atomicAdd(&g_gat[(size_t)d_ * D + d], w * xl[(size_t)s_ * D + d]);
    }
}

// h += gat + bias (bias broadcast over rows)
__global__ void add_gat_kernel(const float* __restrict__ bias, int n)
{
    int i = blockIdx.x * blockDim.x + threadIdx.x;
    if (i >= n * D) return;
    g_h[i] += g_gat[i] + bias[i & (D - 1)];
}

// ---------------- pooling ----------------
// score per node: s = sum_d ta[n,d]*tb[n,d]*Wc[d] + bc
__global__ void pool_score_kernel(const float* __restrict__ ta, const float* __restrict__ tb,
                                  const float* __restrict__ Wc, const float* __restrict__ bc, int n)
{
    int w = (blockIdx.x * blockDim.x + threadIdx.x) >> 5;
    int lane = threadIdx.x & 31;
    if (w >= n) return;
    float acc = 0.f;
#pragma unroll
    for (int i = 0; i < 4; i++) {
        int d = lane + 32 * i;
        acc += ta[(size_t)w * D + d] * tb[(size_t)w * D + d] * Wc[d];
    }
#pragma unroll
    for (int off = 16; off > 0; off >>= 1) acc += __shfl_xor_sync(0xFFFFFFFFu, acc, off);
    if (lane == 0) g_pool_s[w] = acc + bc[0];
}

__global__ void pool_max_kernel(int n)
{
    __shared__ float sm[256];
    int t = threadIdx.x;
    float m = -1e30f;
    for (int i = blockIdx.x * blockDim.x + t; i < n; i += gridDim.x * blockDim.x)
        m = fmaxf(m, g_pool_s[i]);
    sm[t] = m;
    __syncthreads();
    for (int s = 128; s > 0; s >>= 1) {
        if (t < s) sm[t] = fmaxf(sm[t], sm[t + s]);
        __syncthreads();
    }
    if (t == 0) atomicMax(&g_maxu, fenc(sm[0]));
}

// weighted accumulate: hp += exp(s - max) * h[n]; sumw += exp(...)
__global__ void pool_accum_kernel(int n)
{
    __shared__ float sacc[D];
    int t = threadIdx.x;
    int lane = t & 31;
    int wid = t >> 5;
    if (t < D) sacc[t] = 0.f;
    __syncthreads();
    float mx = fdec(g_maxu);
    float racc[4] = {0.f, 0.f, 0.f, 0.f};
    float wsum = 0.f;
    int nwarps = (gridDim.x * blockDim.x) >> 5;
    for (int nd = (blockIdx.x * blockDim.x + t) >> 5; nd < n; nd += nwarps) {
        float w = expf(g_pool_s[nd] - mx);
        if (lane == 0) wsum += w;
#pragma unroll
        for (int i = 0; i < 4; i++)
            racc[i] += w * g_h[(size_t)nd * D + lane + 32 * i];
    }
#pragma unroll
    for (int i = 0; i < 4; i++) atomicAdd(&sacc[lane + 32 * i], racc[i]);
    __syncthreads();
    if (t < D) atomicAdd(&g_hp[t], sacc[t]);
    if (lane == 0 && wsum != 0.f) atomicAdd(&g_sumw, wsum);
    (void)wid;
}

// ---------------- final head (single block, 128 threads) ----------------
__global__ void final_kernel(const float* __restrict__ rho_W, const float* __restrict__ rho_b,
                             const float* __restrict__ cls_W, const float* __restrict__ cls_b,
                             float* __restrict__ out)
{
    __shared__ float hp[D];
    __shared__ float hr[D];
    __shared__ float slog[4];
    int t = threadIdx.x;
    hp[t] = g_hp[t] / g_sumw;
    __syncthreads();
    float a = rho_b[t];
#pragma unroll 4
    for (int k = 0; k < D; k++) a += hp[k] * rho_W[k * D + t];
    hr[t] = a > 0.f ? a : 0.f;
    __syncthreads();
    if (t < 4) {
        float lg = cls_b[t];
#pragma unroll 4
        for (int d = 0; d < D; d++) lg += hr[d] * cls_W[d * 4 + t];
        slog[t] = lg;
    }
    __syncthreads();
    if (t == 0) {
        float hz[4], S[4];
        int am = 0;
        float best = slog[0];
        for (int c = 0; c < 4; c++) {
            hz[c] = 1.f / (1.f + expf(-slog[c]));
            if (slog[c] > best) { best = slog[c]; am = c; }
        }
        S[0] = 1.f - hz[0];
        for (int c = 1; c < 4; c++) S[c] = S[c - 1] * (1.f - hz[c]);
        for (int c = 0; c < 4; c++) out[c] = hz[c];
        for (int c = 0; c < 4; c++) out[4 + c] = S[c];
        out[8] = (float)am;
        for (int c = 0; c < 4; c++) out[9 + c] = slog[c];
    }
}

// ---------------- launch ----------------
extern "C" void kernel_launch(void* const* d_in, const int* in_sizes, int n_in,
                              void* d_out, int out_size)
{
    const float* x      = (const float*)d_in[0];
    const int*   ei     = (const int*)d_in[1];
    const float* emb_W  = (const float*)d_in[2];
    const float* emb_b  = (const float*)d_in[3];
    const float* ln1_g  = (const float*)d_in[4];
    const float* ln1_b  = (const float*)d_in[5];
    const float* gat_Wl = (const float*)d_in[6];
    const float* gat_bl = (const float*)d_in[7];
    const float* gat_Wr = (const float*)d_in[8];
    const float* gat_br = (const float*)d_in[9];
    const float* gat_att  = (const float*)d_in[10];
    const float* gat_bias = (const float*)d_in[11];
    const float* w1s[3] = {(const float*)d_in[12], (const float*)d_in[14], (const float*)d_in[16]};
    const float* w2s[3] = {(const float*)d_in[13], (const float*)d_in[15], (const float*)d_in[17]};
    const float* attn_Wa = (const float*)d_in[18];
    const float* attn_ba = (const float*)d_in[19];
    const float* attn_Wb = (const float*)d_in[20];
    const float* attn_bb = (const float*)d_in[21];
    const float* attn_Wc = (const float*)d_in[22];
    const float* attn_bc = (const float*)d_in[23];
    const float* rho_W   = (const float*)d_in[24];
    const float* rho_b   = (const float*)d_in[25];
    const float* cls_W   = (const float*)d_in[26];
    const float* cls_b   = (const float*)d_in[27];
    float* out = (float*)d_out;

    int n  = in_sizes[0] / 512;     // 50000
    int E  = in_sizes[1] / 2;       // 800000
    int E2 = E + n;

    float* p_h;    cudaGetSymbolAddress((void**)&p_h,    g_h);
    float* p_hn;   cudaGetSymbolAddress((void**)&p_hn,   g_hn);
    float* p_xl;   cudaGetSymbolAddress((void**)&p_xl,   g_xl);
    float* p_xr;   cudaGetSymbolAddress((void**)&p_xr,   g_xr);
    float* p_gat;  cudaGetSymbolAddress((void**)&p_gat,  g_gat);
    float* p_hid;  cudaGetSymbolAddress((void**)&p_hid,  g_hid);
    float* p_den;  cudaGetSymbolAddress((void**)&p_den,  g_denom);
    unsigned* p_smax; cudaGetSymbolAddress((void**)&p_smax, g_smax);

    dim3 blk(256);
    int rowBlocks = (n + 127) / 128;

    // embedding: h = relu(x @ emb_W + emb_b)
    sgemm_kernel<<<dim3(rowBlocks, 1), blk>>>(x, emb_W, emb_b, p_h, n, 512, 128, ACT_RELU, 0);

    int warpGrid  = (n * 32 + 255) / 256;
    int edgeWGrid = ((long long)E2 * 32 + 255) / 256;
    int edgeTGrid = (E2 + 255) / 256;

    for (int i = 0; i < 3; i++) {
        ln_kernel<<<warpGrid, blk>>>(p_h, ln1_g + i * D, ln1_b + i * D, p_hn, n);
        sgemm_kernel<<<dim3(rowBlocks, 1), blk>>>(p_hn, gat_Wl + i * D * D, gat_bl + i * D, p_xl, n, D, D, ACT_NONE, 0);
        sgemm_kernel<<<dim3(rowBlocks, 1), blk>>>(p_hn, gat_Wr + i * D * D, gat_br + i * D, p_xr, n, D, D, ACT_NONE, 0);

        zero_u<<<(n + 255) / 256, blk>>>(p_smax, n);
        zero_f<<<(n + 255) / 256, blk>>>(p_den, n);
        zero_f<<<(n * D + 255) / 256, blk>>>(p_gat, n * D);

        edge_score_kernel<<<edgeWGrid, blk>>>(p_xl, p_xr, gat_att + i * D, ei, E, n);
        edge_exp_kernel<<<edgeTGrid, blk>>>(ei, E, n);
        edge_scatter_kernel<<<edgeWGrid, blk>>>(p_xl, ei, E, n);
        add_gat_kernel<<<(n * D + 255) / 256, blk>>>(gat_bias + i * D, n);

        // MLP: h += gelu(h @ w1) @ w2   (hidden = 128*(i+1))
        int H = D * (i + 1);
        sgemm_kernel<<<dim3(rowBlocks, H / 128), blk>>>(p_h, w1s[i], nullptr, p_hid, n, D, H, ACT_GELU, 0);
        sgemm_kernel<<<dim3(rowBlocks, 1), blk>>>(p_hid, w2s[i], nullptr, p_h, n, H, D, ACT_NONE, 1);
    }

    // pooling: ta = tanh(h@Wa+ba), tb = sigmoid(h@Wb+bb)
    sgemm_kernel<<<dim3(rowBlocks, 1), blk>>>(p_h, attn_Wa, attn_ba, p_xl, n, D, D, ACT_TANH, 0);
    sgemm_kernel<<<dim3(rowBlocks, 1), blk>>>(p_h, attn_Wb, attn_bb, p_xr, n, D, D, ACT_SIGM, 0);

    init_pool_kernel<<<1, 128>>>();
    pool_score_kernel<<<warpGrid, blk>>>(p_xl, p_xr, attn_Wc, attn_bc, n);
    pool_max_kernel<<<160, blk>>>(n);
    pool_accum_kernel<<<296, blk>>>(n);
    final_kernel<<<1, 128>>>(rho_W, rho_b, cls_W, cls_b, out);

    (void)n_in; (void)out_size;
}

// round 2
// speedup vs baseline: 1.6498x; 1.6498x over previous
#include <cuda_runtime.h>
#include <math.h>
#include <stdint.h>

// ---------------- problem constants ----------------
#define NMAX 50000
#define EMAX 800000
#define E2MAX (EMAX + NMAX)
#define D 128
#define HMAX 384

// ---------------- scratch (device globals; no mallocs allowed) ----------------
__device__ float g_h [NMAX * D];
__device__ float g_hn[NMAX * D];
__device__ float g_xl[NMAX * D];
__device__ float g_xr[NMAX * D];
__device__ float g_hid[NMAX * HMAX];
__device__ float g_score[E2MAX];
__device__ float g_ex[E2MAX];
__device__ unsigned g_smax[NMAX];
__device__ float g_denom[NMAX];
__device__ float g_pool_s[NMAX];
__device__ float g_hp[D];
__device__ float g_sumw;
__device__ unsigned g_maxu;

// ---------------- helpers ----------------
__device__ __forceinline__ unsigned fenc(float f) {
    unsigned b = __float_as_uint(f);
    return (b & 0x80000000u) ? ~b : (b | 0x80000000u);
}
__device__ __forceinline__ float fdec(unsigned u) {
    return __uint_as_float((u & 0x80000000u) ? (u & 0x7FFFFFFFu) : ~u);
}
__device__ __forceinline__ uint32_t f2tf(float f) {
    uint32_t u;
    asm("cvt.rna.tf32.f32 %0, %1;" : "=r"(u) : "f"(f));
    return u;
}

#define ACT_NONE 0
#define ACT_RELU 1
#define ACT_GELU 2
#define ACT_TANH 3
#define ACT_SIGM 4

__device__ __forceinline__ float apply_act(float v, int act) {
    switch (act) {
        case ACT_RELU: return v > 0.f ? v : 0.f;
        case ACT_GELU: return 0.5f * v * (1.f + erff(v * 0.70710678118654752f));
        case ACT_TANH: return tanhf(v);
        case ACT_SIGM: return 1.f / (1.f + expf(-v));
        default: return v;
    }
}

// ---------------- zero / init kernels ----------------
__global__ void zero_f(float* p, int n) {
    int i = blockIdx.x * blockDim.x + threadIdx.x;
    if (i < n) p[i] = 0.f;
}
__global__ void zero_u(unsigned* p, int n) {
    int i = blockIdx.x * blockDim.x + threadIdx.x;
    if (i < n) p[i] = 0u;
}
__global__ void init_pool_kernel() {
    int t = threadIdx.x;
    g_hp[t] = 0.f;
    if (t == 0) { g_sumw = 0.f; g_maxu = 0u; }
}

// ---------------- tf32 tensor-core GEMM ----------------
// C[n,M] = act(A[n,K] @ B[K,M] + bias) (+ optional residual add into C)
// Block tile 128x128, BK=32, 256 threads = 8 warps (4x2), warp tile 32x64,
// mma.sync.m16n8k8.tf32, fp32 accumulate.
__global__ __launch_bounds__(256, 2)
void tgemm_kernel(const float* __restrict__ A, const float* __restrict__ B,
                  const float* __restrict__ bias, float* __restrict__ C,
                  int n, int K, int M, int act, int residual)
{
    __shared__ uint32_t sA[128][36];   // [m][k], pad -> conflict-free frag loads
    __shared__ uint32_t sB[32][136];   // [k][n], pad 8

    int tid  = threadIdx.x;
    int lane = tid & 31;
    int warp = tid >> 5;
    int g    = lane >> 2;   // 0..7
    int tig  = lane & 3;    // 0..3
    int mW   = (warp & 3) * 32;
    int nW   = (warp >> 2) * 64;
    int rowBase = blockIdx.x * 128;
    int colBase = blockIdx.y * 128;

    float acc[2][8][4];
#pragma unroll
    for (int mt = 0; mt < 2; mt++)
#pragma unroll
        for (int nt = 0; nt < 8; nt++)
#pragma unroll
            for (int c = 0; c < 4; c++) acc[mt][nt][c] = 0.f;

    for (int k0 = 0; k0 < K; k0 += 32) {
        // A tile: 128 rows x 32 k  (1024 float4 total, 4 per thread)
#pragma unroll
        for (int i = 0; i < 4; i++) {
            int idx = tid + 256 * i;
            int r   = idx >> 3;
            int kc  = (idx & 7) * 4;
            int gr  = rowBase + r;
            float4 v = make_float4(0.f, 0.f, 0.f, 0.f);
            if (gr < n) v = *reinterpret_cast<const float4*>(A + (size_t)gr * K + k0 + kc);
            sA[r][kc + 0] = f2tf(v.x);
            sA[r][kc + 1] = f2tf(v.y);
            sA[r][kc + 2] = f2tf(v.z);
            sA[r][kc + 3] = f2tf(v.w);
        }
        // B tile: 32 k x 128 cols
#pragma unroll
        for (int i = 0; i < 4; i++) {
            int idx = tid + 256 * i;
            int kr  = idx >> 5;
            int c   = (idx & 31) * 4;
            float4 v = *reinterpret_cast<const float4*>(B + (size_t)(k0 + kr) * M + colBase + c);
            sB[kr][c + 0] = f2tf(v.x);
            sB[kr][c + 1] = f2tf(v.y);
            sB[kr][c + 2] = f2tf(v.z);
            sB[kr][c + 3] = f2tf(v.w);
        }
        __syncthreads();

#pragma unroll
        for (int kt = 0; kt < 4; kt++) {
            int kb = kt * 8;
            uint32_t a[2][4], b[8][2];
#pragma unroll
            for (int mt = 0; mt < 2; mt++) {
                int mb = mW + mt * 16;
                a[mt][0] = sA[mb + g    ][kb + tig    ];
                a[mt][1] = sA[mb + g + 8][kb + tig    ];
                a[mt][2] = sA[mb + g    ][kb + tig + 4];
                a[mt][3] = sA[mb + g + 8][kb + tig + 4];
            }
#pragma unroll
            for (int nt = 0; nt < 8; nt++) {
                int nb = nW + nt * 8;
                b[nt][0] = sB[kb + tig    ][nb + g];
                b[nt][1] = sB[kb + tig + 4][nb + g];
            }
#pragma unroll
            for (int mt = 0; mt < 2; mt++)
#pragma unroll
                for (int nt = 0; nt < 8; nt++) {
                    asm volatile(
                        "mma.sync.aligned.m16n8k8.row.col.f32.tf32.tf32.f32 "
                        "{%0,%1,%2,%3}, {%4,%5,%6,%7}, {%8,%9}, {%0,%1,%2,%3};"
                        : "+f"(acc[mt][nt][0]), "+f"(acc[mt][nt][1]),
                          "+f"(acc[mt][nt][2]), "+f"(acc[mt][nt][3])
                        : "r"(a[mt][0]), "r"(a[mt][1]), "r"(a[mt][2]), "r"(a[mt][3]),
                          "r"(b[nt][0]), "r"(b[nt][1]));
                }
        }
        __syncthreads();
    }

    // epilogue
#pragma unroll
    for (int mt = 0; mt < 2; mt++) {
#pragma unroll
        for (int half = 0; half < 2; half++) {
            int gr = rowBase + mW + mt * 16 + g + half * 8;
            if (gr >= n) continue;
#pragma unroll
            for (int nt = 0; nt < 8; nt++) {
#pragma unroll
                for (int j = 0; j < 2; j++) {
                    int gc = colBase + nW + nt * 8 + tig * 2 + j;
                    float v = acc[mt][nt][half * 2 + j];
                    if (bias) v += bias[gc];
                    v = apply_act(v, act);
                    size_t o = (size_t)gr * M + gc;
                    if (residual) C[o] = C[o] + v; else C[o] = v;
                }
            }
        }
    }
}

// ---------------- LayerNorm (warp per row, D=128) ----------------
__global__ void ln_kernel(const float* __restrict__ X, const float* __restrict__ g,
                          const float* __restrict__ b, float* __restrict__ Y, int n)
{
    int w = (blockIdx.x * blockDim.x + threadIdx.x) >> 5;
    int lane = threadIdx.x & 31;
    if (w >= n) return;
    const float* xr = X + (size_t)w * D;
    float v[4], s = 0.f, s2 = 0.f;
#pragma unroll
    for (int i = 0; i < 4; i++) {
        v[i] = xr[lane + 32 * i];
        s += v[i];
        s2 += v[i] * v[i];
    }
#pragma unroll
    for (int off = 16; off > 0; off >>= 1) {
        s  += __shfl_xor_sync(0xFFFFFFFFu, s,  off);
        s2 += __shfl_xor_sync(0xFFFFFFFFu, s2, off);
    }
    float mu = s * (1.f / 128.f);
    float var = s2 * (1.f / 128.f) - mu * mu;
    float rstd = rsqrtf(var + 1e-5f);
    float* yr = Y + (size_t)w * D;
#pragma unroll
    for (int i = 0; i < 4; i++) {
        int d = lane + 32 * i;
        yr[d] = (v[i] - mu) * rstd * g[d] + b[d];
    }
}

// ---------------- GATv2 edge passes ----------------
__global__ void edge_score_kernel(const float* __restrict__ xl, const float* __restrict__ xr,
                                  const float* __restrict__ att, const int* __restrict__ ei,
                                  int E, int n)
{
    int e = (blockIdx.x * blockDim.x + threadIdx.x) >> 5;
    int lane = threadIdx.x & 31;
    int E2 = E + n;
    if (e >= E2) return;
    int s_, d_;
    if (e < E) { s_ = ei[e]; d_ = ei[E + e]; } else { s_ = d_ = e - E; }
    float acc = 0.f;
#pragma unroll
    for (int i = 0; i < 4; i++) {
        int d = lane + 32 * i;
        float v = xl[(size_t)s_ * D + d] + xr[(size_t)d_ * D + d];
        v = v > 0.f ? v : 0.2f * v;
        acc += v * att[d];
    }
#pragma unroll
    for (int off = 16; off > 0; off >>= 1) acc += __shfl_xor_sync(0xFFFFFFFFu, acc, off);
    if (lane == 0) {
        g_score[e] = acc;
        atomicMax(&g_smax[d_], fenc(acc));
    }
}

__global__ void edge_exp_kernel(const int* __restrict__ ei, int E, int n)
{
    int e = blockIdx.x * blockDim.x + threadIdx.x;
    int E2 = E + n;
    if (e >= E2) return;
    int d_ = (e < E) ? ei[E + e] : (e - E);
    float ex = expf(g_score[e] - fdec(g_smax[d_]));
    g_ex[e] = ex;
    atomicAdd(&g_denom[d_], ex);
}

// scatter directly into g_h (bias already added to h)
__global__ void edge_scatter_kernel(const float* __restrict__ xl, const int* __restrict__ ei,
                                    int E, int n)
{
    int e = (blockIdx.x * blockDim.x + threadIdx.x) >> 5;
    int lane = threadIdx.x & 31;
    int E2 = E + n;
    if (e >= E2) return;
    int s_, d_;
    if (e < E) { s_ = ei[e]; d_ = ei[E + e]; } else { s_ = d_ = e - E; }
    float w = g_ex[e] / g_denom[d_];
#pragma unroll
    for (int i = 0; i < 4; i++) {
        int d = lane + 32 * i;
        atomicAdd(&g_h[(size_t)d_ * D + d], w * xl[(size_t)s_ * D + d]);
    }
}

// h += bias (broadcast over rows)
__global__ void add_bias_kernel(const float* __restrict__ bias, int n)
{
    int i = blockIdx.x * blockDim.x + threadIdx.x;
    if (i >= n * D) return;
    g_h[i] += bias[i & (D - 1)];
}

// ---------------- pooling ----------------
__global__ void pool_score_kernel(const float* __restrict__ ta, const float* __restrict__ tb,
                                  const float* __restrict__ Wc, const float* __restrict__ bc, int n)
{
    int w = (blockIdx.x * blockDim.x + threadIdx.x) >> 5;
    int lane = threadIdx.x & 31;
    if (w >= n) return;
    float acc = 0.f;
#pragma unroll
    for (int i = 0; i < 4; i++) {
        int d = lane + 32 * i;
        acc += ta[(size_t)w * D + d] * tb[(size_t)w * D + d] * Wc[d];
    }
#pragma unroll
    for (int off = 16; off > 0; off >>= 1) acc += __shfl_xor_sync(0xFFFFFFFFu, acc, off);
    if (lane == 0) g_pool_s[w] = acc + bc[0];
}

__global__ void pool_max_kernel(int n)
{
    __shared__ float sm[256];
    int t = threadIdx.x;
    float m = -1e30f;
    for (int i = blockIdx.x * blockDim.x + t; i < n; i += gridDim.x * blockDim.x)
        m = fmaxf(m, g_pool_s[i]);
    sm[t] = m;
    __syncthreads();
    for (int s = 128; s > 0; s >>= 1) {
        if (t < s) sm[t] = fmaxf(sm[t], sm[t + s]);
        __syncthreads();
    }
    if (t == 0) atomicMax(&g_maxu, fenc(sm[0]));
}

__global__ void pool_accum_kernel(int n)
{
    __shared__ float sacc[D];
    int t = threadIdx.x;
    int lane = t & 31;
    if (t < D) sacc[t] = 0.f;
    __syncthreads();
    float mx = fdec(g_maxu);
    float racc[4] = {0.f, 0.f, 0.f, 0.f};
    float wsum = 0.f;
    int nwarps = (gridDim.x * blockDim.x) >> 5;
    for (int nd = (blockIdx.x * blockDim.x + t) >> 5; nd < n; nd += nwarps) {
        float w = expf(g_pool_s[nd] - mx);
        if (lane == 0) wsum += w;
#pragma unroll
        for (int i = 0; i < 4; i++)
            racc[i] += w * g_h[(size_t)nd * D + lane + 32 * i];
    }
#pragma unroll
    for (int i = 0; i < 4; i++) atomicAdd(&sacc[lane + 32 * i], racc[i]);
    __syncthreads();
    if (t < D) atomicAdd(&g_hp[t], sacc[t]);
    if (lane == 0 && wsum != 0.f) atomicAdd(&g_sumw, wsum);
}

// ---------------- final head ----------------
__global__ void final_kernel(const float* __restrict__ rho_W, const float* __restrict__ rho_b,
                             const float* __restrict__ cls_W, const float* __restrict__ cls_b,
                             float* __restrict__ out)
{
    __shared__ float hp[D];
    __shared__ float hr[D];
    __shared__ float slog[4];
    int t = threadIdx.x;
    hp[t] = g_hp[t] / g_sumw;
    __syncthreads();
    float a = rho_b[t];
#pragma unroll 4
    for (int k = 0; k < D; k++) a += hp[k] * rho_W[k * D + t];
    hr[t] = a > 0.f ? a : 0.f;
    __syncthreads();
    if (t < 4) {
        float lg = cls_b[t];
#pragma unroll 4
        for (int d = 0; d < D; d++) lg += hr[d] * cls_W[d * 4 + t];
        slog[t] = lg;
    }
    __syncthreads();
    if (t == 0) {
        float hz[4], S[4];
        int am = 0;
        float best = slog[0];
        for (int c = 0; c < 4; c++) {
            hz[c] = 1.f / (1.f + expf(-slog[c]));
            if (slog[c] > best) { best = slog[c]; am = c; }
        }
        S[0] = 1.f - hz[0];
        for (int c = 1; c < 4; c++) S[c] = S[c - 1] * (1.f - hz[c]);
        for (int c = 0; c < 4; c++) out[c] = hz[c];
        for (int c = 0; c < 4; c++) out[4 + c] = S[c];
        out[8] = (float)am;
        for (int c = 0; c < 4; c++) out[9 + c] = slog[c];
    }
}

// ---------------- launch ----------------
extern "C" void kernel_launch(void* const* d_in, const int* in_sizes, int n_in,
                              void* d_out, int out_size)
{
    const float* x      = (const float*)d_in[0];
    const int*   ei     = (const int*)d_in[1];
    const float* emb_W  = (const float*)d_in[2];
    const float* emb_b  = (const float*)d_in[3];
    const float* ln1_g  = (const float*)d_in[4];
    const float* ln1_b  = (const float*)d_in[5];
    const float* gat_Wl = (const float*)d_in[6];
    const float* gat_bl = (const float*)d_in[7];
    const float* gat_Wr = (const float*)d_in[8];
    const float* gat_br = (const float*)d_in[9];
    const float* gat_att  = (const float*)d_in[10];
    const float* gat_bias = (const float*)d_in[11];
    const float* w1s[3] = {(const float*)d_in[12], (const float*)d_in[14], (const float*)d_in[16]};
    const float* w2s[3] = {(const float*)d_in[13], (const float*)d_in[15], (const float*)d_in[17]};
    const float* attn_Wa = (const float*)d_in[18];
    const float* attn_ba = (const float*)d_in[19];
    const float* attn_Wb = (const float*)d_in[20];
    const float* attn_bb = (const float*)d_in[21];
    const float* attn_Wc = (const float*)d_in[22];
    const float* attn_bc = (const float*)d_in[23];
    const float* rho_W   = (const float*)d_in[24];
    const float* rho_b   = (const float*)d_in[25];
    const float* cls_W   = (const float*)d_in[26];
    const float* cls_b   = (const float*)d_in[27];
    float* out = (float*)d_out;

    int n  = in_sizes[0] / 512;     // 50000
    int E  = in_sizes[1] / 2;       // 800000
    int E2 = E + n;

    float* p_h;    cudaGetSymbolAddress((void**)&p_h,    g_h);
    float* p_hn;   cudaGetSymbolAddress((void**)&p_hn,   g_hn);
    float* p_xl;   cudaGetSymbolAddress((void**)&p_xl,   g_xl);
    float* p_xr;   cudaGetSymbolAddress((void**)&p_xr,   g_xr);
    float* p_hid;  cudaGetSymbolAddress((void**)&p_hid,  g_hid);
    float* p_den;  cudaGetSymbolAddress((void**)&p_den,  g_denom);
    unsigned* p_smax; cudaGetSymbolAddress((void**)&p_smax, g_smax);

    dim3 blk(256);
    int rowBlocks = (n + 127) / 128;

    // embedding: h = relu(x @ emb_W + emb_b)
    tgemm_kernel<<<dim3(rowBlocks, 1), blk>>>(x, emb_W, emb_b, p_h, n, 512, 128, ACT_RELU, 0);

    int warpGrid  = (n * 32 + 255) / 256;
    int edgeWGrid = (int)(((long long)E2 * 32 + 255) / 256);
    int edgeTGrid = (E2 + 255) / 256;

    for (int i = 0; i < 3; i++) {
        ln_kernel<<<warpGrid, blk>>>(p_h, ln1_g + i * D, ln1_b + i * D, p_hn, n);
        tgemm_kernel<<<dim3(rowBlocks, 1), blk>>>(p_hn, gat_Wl + i * D * D, gat_bl + i * D, p_xl, n, D, D, ACT_NONE, 0);
        tgemm_kernel<<<dim3(rowBlocks, 1), blk>>>(p_hn, gat_Wr + i * D * D, gat_br + i * D, p_xr, n, D, D, ACT_NONE, 0);

        zero_u<<<(n + 255) / 256, blk>>>(p_smax, n);
        zero_f<<<(n + 255) / 256, blk>>>(p_den, n);
        add_bias_kernel<<<(n * D + 255) / 256, blk>>>(gat_bias + i * D, n);

        edge_score_kernel<<<edgeWGrid, blk>>>(p_xl, p_xr, gat_att + i * D, ei, E, n);
        edge_exp_kernel<<<edgeTGrid, blk>>>(ei, E, n);
        edge_scatter_kernel<<<edgeWGrid, blk>>>(p_xl, ei, E, n);

        // MLP: h += gelu(h @ w1) @ w2   (hidden = 128*(i+1))
        int H = D * (i + 1);
        tgemm_kernel<<<dim3(rowBlocks, H / 128), blk>>>(p_h, w1s[i], nullptr, p_hid, n, D, H, ACT_GELU, 0);
        tgemm_kernel<<<dim3(rowBlocks, 1), blk>>>(p_hid, w2s[i], nullptr, p_h, n, H, D, ACT_NONE, 1);
    }

    // pooling: ta = tanh(h@Wa+ba), tb = sigmoid(h@Wb+bb)
    tgemm_kernel<<<dim3(rowBlocks, 1), blk>>>(p_h, attn_Wa, attn_ba, p_xl, n, D, D, ACT_TANH, 0);
    tgemm_kernel<<<dim3(rowBlocks, 1), blk>>>(p_h, attn_Wb, attn_bb, p_xr, n, D, D, ACT_SIGM, 0);

    init_pool_kernel<<<1, 128>>>();
    pool_score_kernel<<<warpGrid, blk>>>(p_xl, p_xr, attn_Wc, attn_bc, n);
    pool_max_kernel<<<160, blk>>>(n);
    pool_accum_kernel<<<296, blk>>>(n);
    final_kernel<<<1, 128>>>(rho_W, rho_b, cls_W, cls_b, out);

    (void)n_in; (void)out_size;
}